// round 4
// baseline (speedup 1.0000x reference)
#include <cuda_runtime.h>
#include <cuda_bf16.h>

// Problem dims
#define BATCH 2
#define SEQ   2048
#define DIM   2048
#define NHEAD 16
#define HDIM  128
#define MFF   8192
#define TOK   (BATCH * SEQ)          // 4096
#define QKVW  (3 * NHEAD * HDIM)     // 6144

// ---------------- scratch (device globals; no allocation) ----------------
__device__ float g_h1   [(size_t)TOK * DIM];        //  33.5 MB
__device__ float g_qkv  [(size_t)TOK * QKVW];       // 100.7 MB
__device__ float g_scores[(size_t)BATCH * NHEAD * SEQ * SEQ]; // 536.9 MB
__device__ float g_attn [(size_t)TOK * DIM];
__device__ float g_x2   [(size_t)TOK * DIM];
__device__ float g_h2   [(size_t)TOK * DIM];
__device__ float g_gate [(size_t)TOK * MFF];        // 134 MB
__device__ float g_hu   [(size_t)TOK * MFF];        // 134 MB

// ---------------- RMSNorm: one block per row of 2048 ----------------
__global__ void rmsnorm_kernel(const float* __restrict__ x,
                               const float* __restrict__ g,
                               float* __restrict__ y)
{
    long long row = blockIdx.x;
    const float* xr = x + row * DIM;
    float* yr = y + row * DIM;
    int tid = threadIdx.x;

    float v[8];
    float ss = 0.f;
#pragma unroll
    for (int i = 0; i < 8; i++) {
        v[i] = xr[tid + (i << 8)];
        ss += v[i] * v[i];
    }
    __shared__ float sh[8];
#pragma unroll
    for (int o = 16; o > 0; o >>= 1) ss += __shfl_xor_sync(0xffffffffu, ss, o);
    if ((tid & 31) == 0) sh[tid >> 5] = ss;
    __syncthreads();
    if (tid < 32) {
        float t = (tid < 8) ? sh[tid] : 0.f;
#pragma unroll
        for (int o = 4; o > 0; o >>= 1) t += __shfl_xor_sync(0xffffffffu, t, o);
        if (tid == 0) sh[0] = t;
    }
    __syncthreads();
    float r = rsqrtf(sh[0] * (1.0f / DIM) + 1e-6f);
#pragma unroll
    for (int i = 0; i < 8; i++)
        yr[tid + (i << 8)] = v[i] * r * g[tid + (i << 8)];
}

// ---------------- row softmax over SEQ=2048 columns ----------------
__global__ void softmax_kernel(float* __restrict__ sc)
{
    long long row = blockIdx.x;
    float* p = sc + row * SEQ;
    int tid = threadIdx.x;

    float v[8];
    float mx = -3.4e38f;
#pragma unroll
    for (int i = 0; i < 8; i++) {
        v[i] = p[tid + (i << 8)];
        mx = fmaxf(mx, v[i]);
    }
    __shared__ float sh[8];
#pragma unroll
    for (int o = 16; o > 0; o >>= 1) mx = fmaxf(mx, __shfl_xor_sync(0xffffffffu, mx, o));
    if ((tid & 31) == 0) sh[tid >> 5] = mx;
    __syncthreads();
    if (tid < 32) {
        float t = (tid < 8) ? sh[tid] : -3.4e38f;
#pragma unroll
        for (int o = 4; o > 0; o >>= 1) t = fmaxf(t, __shfl_xor_sync(0xffffffffu, t, o));
        if (tid == 0) sh[0] = t;
    }
    __syncthreads();
    mx = sh[0];

    float s = 0.f;
#pragma unroll
    for (int i = 0; i < 8; i++) {
        v[i] = __expf(v[i] - mx);   // masked (-1e30) entries underflow to exactly 0
        s += v[i];
    }
    __syncthreads();  // everyone has read sh[0]
#pragma unroll
    for (int o = 16; o > 0; o >>= 1) s += __shfl_xor_sync(0xffffffffu, s, o);
    if ((tid & 31) == 0) sh[tid >> 5] = s;
    __syncthreads();
    if (tid < 32) {
        float t = (tid < 8) ? sh[tid] : 0.f;
#pragma unroll
        for (int o = 4; o > 0; o >>= 1) t += __shfl_xor_sync(0xffffffffu, t, o);
        if (tid == 0) sh[0] = t;
    }
    __syncthreads();
    float inv = 1.0f / sh[0];
#pragma unroll
    for (int i = 0; i < 8; i++)
        p[tid + (i << 8)] = v[i] * inv;
}

// ---------------- tiled fp32 GEMM, 128x128x8, 256 threads, 8x8 microtile ----
// C[m,n] = sum_k A[m,k] * (TRANS_B ? B[n,k] : B[k,n])   (+ fused epilogue)
// Batched via blockIdx.z: off = (z>>4)*s?0 + (z&15)*s?1   (z=0 for non-batched)
#define EPI_NONE   0
#define EPI_ADD    1   // C = acc + extra[m*ldc+n]
#define EPI_SILU   2   // C = acc * silu(extra[m*ldc+n])
#define EPI_CAUSAL 3   // C = (n<=m) ? acc*alpha : -1e30

template<bool TRANS_B, int EPI, bool CAUSAL_K>
__global__ __launch_bounds__(256, 2)
void gemm_kernel(const float* __restrict__ A, const float* __restrict__ Bm,
                 float* __restrict__ C, const float* __restrict__ extra,
                 int Mdim, int Ndim, int Kdim, int lda, int ldb, int ldc,
                 long long sA0, long long sA1, long long sB0, long long sB1,
                 long long sC0, long long sC1, float alpha)
{
    int z = blockIdx.z;
    int zb = z >> 4, zh = z & 15;
    A  += zb * sA0 + zh * sA1;
    Bm += zb * sB0 + zh * sB1;
    C  += zb * sC0 + zh * sC1;

    int m0 = blockIdx.y << 7;
    int n0 = blockIdx.x << 7;
    int tid = threadIdx.x;

    if (EPI == EPI_CAUSAL && n0 > m0 + 127) {
        // fully masked block: fill and exit (saves ~half the score flops)
        for (int i = tid; i < 128 * 128; i += 256) {
            int r = i >> 7, c = i & 127;
            C[(long long)(m0 + r) * ldc + n0 + c] = -1e30f;
        }
        return;
    }

    __shared__ __align__(16) float As[8][132];
    __shared__ __align__(16) float Bs[8][132];

    float acc[8][8];
#pragma unroll
    for (int i = 0; i < 8; i++)
#pragma unroll
        for (int j = 0; j < 8; j++) acc[i][j] = 0.f;

    int Keff = CAUSAL_K ? min(Kdim, m0 + 128) : Kdim;

    int aRow = tid >> 1;
    int aK4  = (tid & 1) << 2;
    const float* Ag = A + (long long)(m0 + aRow) * lda + aK4;
    const float* Bg;
    int bRow = tid >> 5;
    int bCol = (tid & 31) << 2;
    if (TRANS_B) Bg = Bm + (long long)(n0 + aRow) * ldb + aK4;
    else         Bg = Bm + (long long)bRow * ldb + n0 + bCol;

    int ty = tid >> 4, tx = tid & 15;

    for (int k0 = 0; k0 < Keff; k0 += 8) {
        float4 av = *(const float4*)(Ag + k0);
        As[aK4 + 0][aRow] = av.x;
        As[aK4 + 1][aRow] = av.y;
        As[aK4 + 2][aRow] = av.z;
        As[aK4 + 3][aRow] = av.w;
        if (TRANS_B) {
            float4 bv = *(const float4*)(Bg + k0);
            Bs[aK4 + 0][aRow] = bv.x;
            Bs[aK4 + 1][aRow] = bv.y;
            Bs[aK4 + 2][aRow] = bv.z;
            Bs[aK4 + 3][aRow] = bv.w;
        } else {
            float4 bv = *(const float4*)(Bg + (long long)k0 * ldb);
            *(float4*)&Bs[bRow][bCol] = bv;
        }
        __syncthreads();
#pragma unroll
        for (int kk = 0; kk < 8; kk++) {
            float ar[8], br[8];
            *(float4*)(ar)     = *(const float4*)&As[kk][ty * 8];
            *(float4*)(ar + 4) = *(const float4*)&As[kk][ty * 8 + 4];
            *(float4*)(br)     = *(const float4*)&Bs[kk][tx * 8];
            *(float4*)(br + 4) = *(const float4*)&Bs[kk][tx * 8 + 4];
#pragma unroll
            for (int i = 0; i < 8; i++)
#pragma unroll
                for (int j = 0; j < 8; j++)
                    acc[i][j] = fmaf(ar[i], br[j], acc[i][j]);
        }
        __syncthreads();
    }

#pragma unroll
    for (int i = 0; i < 8; i++) {
        int m = m0 + ty * 8 + i;
#pragma unroll
        for (int j = 0; j < 8; j++) {
            int n = n0 + tx * 8 + j;
            long long idx = (long long)m * ldc + n;
            float v = acc[i][j];
            if (EPI == EPI_ADD) {
                v += extra[idx];
            } else if (EPI == EPI_SILU) {
                float gt = extra[idx];
                v = v * (gt / (1.f + __expf(-gt)));   // acc(up) * silu(gate)
            } else if (EPI == EPI_CAUSAL) {
                v = (n <= m) ? v * alpha : -1e30f;
            }
            C[idx] = v;
        }
    }
}

// ---------------- launch ----------------
extern "C" void kernel_launch(void* const* d_in, const int* in_sizes, int n_in,
                              void* d_out, int out_size)
{
    const float* x      = (const float*)d_in[0];
    const float* w_qkv  = (const float*)d_in[1];
    const float* w_o    = (const float*)d_in[2];
    const float* w_gate = (const float*)d_in[3];
    const float* w_up   = (const float*)d_in[4];
    const float* w_down = (const float*)d_in[5];
    const float* rms1   = (const float*)d_in[6];
    const float* rms2   = (const float*)d_in[7];
    float* out = (float*)d_out;

    float *h1, *qkv, *scores, *attn, *x2, *h2, *gate, *hu;
    cudaGetSymbolAddress((void**)&h1,     g_h1);
    cudaGetSymbolAddress((void**)&qkv,    g_qkv);
    cudaGetSymbolAddress((void**)&scores, g_scores);
    cudaGetSymbolAddress((void**)&attn,   g_attn);
    cudaGetSymbolAddress((void**)&x2,     g_x2);
    cudaGetSymbolAddress((void**)&h2,     g_h2);
    cudaGetSymbolAddress((void**)&gate,   g_gate);
    cudaGetSymbolAddress((void**)&hu,     g_hu);

    const long long SS  = (long long)SEQ * SEQ;          // 4,194,304
    const long long SQW = (long long)SEQ * QKVW;         // per-batch qkv stride
    const float scale = 0.08838834764831843f;            // 1/sqrt(128)

    // 1. h1 = rmsnorm(x, rms1)
    rmsnorm_kernel<<<TOK, 256>>>(x, rms1, h1);

    // 2. qkv = h1 @ w_qkv            [4096 x 6144 x 2048]
    gemm_kernel<false, EPI_NONE, false><<<dim3(QKVW / 128, TOK / 128, 1), 256>>>(
        h1, w_qkv, qkv, nullptr, TOK, QKVW, DIM, DIM, QKVW, QKVW,
        0, 0, 0, 0, 0, 0, 1.f);

    // 3. scores[b,h] = q kT * scale with causal mask   (batched NT, z = b*16+h)
    gemm_kernel<true, EPI_CAUSAL, false><<<dim3(SEQ / 128, SEQ / 128, BATCH * NHEAD), 256>>>(
        qkv, qkv + NHEAD * HDIM, scores, nullptr,
        SEQ, SEQ, HDIM, QKVW, QKVW, SEQ,
        SQW, HDIM, SQW, HDIM, (long long)NHEAD * SS, SS, scale);

    // 4. row softmax
    softmax_kernel<<<BATCH * NHEAD * SEQ, 256>>>(scores);

    // 5. attn[b,q,h,:] = P @ V       (batched NN, causal K-clip)
    gemm_kernel<false, EPI_NONE, true><<<dim3(1, SEQ / 128, BATCH * NHEAD), 256>>>(
        scores, qkv + 2 * NHEAD * HDIM, attn, nullptr,
        SEQ, HDIM, SEQ, SEQ, QKVW, DIM,
        (long long)NHEAD * SS, SS, SQW, HDIM, (long long)SEQ * DIM, HDIM, 1.f);

    // 6. x2 = x + attn @ w_o
    gemm_kernel<false, EPI_ADD, false><<<dim3(DIM / 128, TOK / 128, 1), 256>>>(
        attn, w_o, x2, x, TOK, DIM, DIM, DIM, DIM, DIM,
        0, 0, 0, 0, 0, 0, 1.f);

    // 7. h2 = rmsnorm(x2, rms2)
    rmsnorm_kernel<<<TOK, 256>>>(x2, rms2, h2);

    // 8. gate = h2 @ w_gate
    gemm_kernel<false, EPI_NONE, false><<<dim3(MFF / 128, TOK / 128, 1), 256>>>(
        h2, w_gate, gate, nullptr, TOK, MFF, DIM, DIM, MFF, MFF,
        0, 0, 0, 0, 0, 0, 1.f);

    // 9. hu = silu(gate) * (h2 @ w_up)
    gemm_kernel<false, EPI_SILU, false><<<dim3(MFF / 128, TOK / 128, 1), 256>>>(
        h2, w_up, hu, gate, TOK, MFF, DIM, DIM, MFF, MFF,
        0, 0, 0, 0, 0, 0, 1.f);

    // 10. out = x2 + hu @ w_down
    gemm_kernel<false, EPI_ADD, false><<<dim3(DIM / 128, TOK / 128, 1), 256>>>(
        hu, w_down, out, x2, TOK, DIM, MFF, MFF, DIM, DIM,
        0, 0, 0, 0, 0, 0, 1.f);
}